// round 13
// baseline (speedup 1.0000x reference)
#include <cuda_runtime.h>
#include <cuda_bf16.h>
#include <cstdint>

#define BINS 20
#define NODES 21
#define NWARPS 8
#define THREADS 256
#define MAXBLOCKS 592
#define SLOTS (2 * BINS)
#define FRAC_BITS 13
#define FRAC_MASK ((1u << FRAC_BITS) - 1u)
#define INV_FRAC_SCALE (1.0f/8192.0f)
#define CNT_SHIFT 20                /* smem u32 pack: cnt<<20 | frac13 */
#define PACK_SCALE 163840.0f        /* BINS << FRAC_BITS = 20*8192 */
#define MAGIC 12582912.0f           /* 1.5 * 2^23: float->fixed trick */
#define MAGIC_BITS 0x4B400000u
#define TOT_SHIFT 36                /* global u64 pack: cnt<<36 | frac_sum */
#define FULLMASK 0xffffffffu

__device__ unsigned long long g_tot[SLOTS];
__device__ unsigned int g_cnt1;
__device__ unsigned int g_done;

// Warp-aggregated accumulate: lanes with the same slot merge via
// match_any + redux; one leader lane issues the (shared) atomic.
// MUST be called by all 32 lanes of the warp (convergent).
__device__ __forceinline__ void hx_accum(unsigned int* my, float x, int g,
                                         bool valid, unsigned int lo,
                                         unsigned int span, unsigned int lanebit,
                                         unsigned int& c1) {
    // Float->fixed via FFMA magic: bits(x*163840 + 1.5*2^23) - MAGIC_BITS
    // == rn(x*163840); k = u>>13, 13-bit frac in low bits.
    unsigned int u = __float_as_uint(fmaf(x, PACK_SCALE, MAGIC)) - MAGIC_BITS;
    unsigned int k = u >> FRAC_BITS;
    c1 += valid ? (unsigned int)g : 0u;
    bool inr = valid && ((k - lo) <= span);
    unsigned int amask = __ballot_sync(FULLMASK, inr);
    if (inr) {
        unsigned int t = (unsigned int)g * BINS + k;
        unsigned int mm = __match_any_sync(amask, t);
        unsigned int pk = (u & FRAC_MASK) | (1u << CNT_SHIFT);
        unsigned int sum = __reduce_add_sync(mm, pk);
        if ((mm & (lanebit - 1u)) == 0u)     // lowest lane in matched group
            atomicAdd(&my[t], sum);
    }
}

// Plain (non-collective) variant for the divergent tail.
__device__ __forceinline__ void hx_accum_plain(unsigned int* my, float x, int g,
                                               unsigned int lo, unsigned int span,
                                               unsigned int& c1) {
    unsigned int u = __float_as_uint(fmaf(x, PACK_SCALE, MAGIC)) - MAGIC_BITS;
    unsigned int k = u >> FRAC_BITS;
    c1 += (unsigned int)g;
    if (k - lo <= span) {
        unsigned int pk = (u & FRAC_MASK) | (1u << CNT_SHIFT);
        atomicAdd(&my[(unsigned int)g * BINS + k], pk);
    }
}

__global__ __launch_bounds__(THREADS, 4)
void hx_fused(const float* __restrict__ yp, const int* __restrict__ s, int n,
              const float* __restrict__ p_a, const float* __restrict__ p_b,
              float* __restrict__ out) {
    __shared__ unsigned int sh[NWARPS][SLOTS];
    __shared__ unsigned int s_c1;
    __shared__ bool s_last;
    const int tid = threadIdx.x;
    const int warp = tid >> 5;
    const unsigned int lanebit = 1u << (tid & 31);

    for (int i = tid; i < NWARPS * SLOTS; i += THREADS)
        (&sh[0][0])[i] = 0u;
    if (tid == 0) s_c1 = 0u;
    __syncthreads();

    // int(20*pct) in Python is computed in double; f32 0.7f*20 = 13.99999976
    // would floor to 13, so snap up with an epsilon before truncation.
    const int a_bin = (int)floorf((float)BINS * __ldg(p_a) + 1e-4f);
    const int b_bin = (int)floorf((float)BINS * __ldg(p_b) + 1e-4f);
    const unsigned int lo   = (unsigned int)max(a_bin - 1, 0);
    const unsigned int hi   = (unsigned int)(min(b_bin, BINS) - 1);
    const unsigned int span = hi - lo;

    unsigned int* my = sh[warp];
    unsigned int c1 = 0;

    const int nvec = n >> 2;
    const float4* __restrict__ yp4 = (const float4*)yp;
    const int4*   __restrict__ s4p = (const int4*)s;
    const int T = gridDim.x * THREADS;

    // Convergent grid-stride loop: all 32 lanes iterate together (clamped
    // loads + valid mask) so the warp collectives in hx_accum are legal.
    #pragma unroll 4
    for (int i = blockIdx.x * THREADS + tid;
         __any_sync(FULLMASK, i < nvec); i += T) {
        bool valid = (i < nvec);
        int ii = valid ? i : (nvec - 1);
        float4 x4 = yp4[ii];
        int4   g4 = s4p[ii];
        hx_accum(my, x4.x, g4.x, valid, lo, span, lanebit, c1);
        hx_accum(my, x4.y, g4.y, valid, lo, span, lanebit, c1);
        hx_accum(my, x4.z, g4.z, valid, lo, span, lanebit, c1);
        hx_accum(my, x4.w, g4.w, valid, lo, span, lanebit, c1);
    }

    // tail (n not divisible by 4) — divergent, plain atomics
    {
        int rem_base = nvec << 2;
        int gtid = blockIdx.x * THREADS + tid;
        if (gtid < n - rem_base) {
            int idx = rem_base + gtid;
            hx_accum_plain(my, yp[idx], s[idx], lo, span, c1);
        }
    }

    // Exact group-1 count: warp redux -> smem -> one global atomic per block.
    c1 = __reduce_add_sync(FULLMASK, c1);
    if ((tid & 31) == 0 && c1) atomicAdd(&s_c1, c1);
    __syncthreads();

    // Reduce warp copies; ONE packed global atomic per slot per block.
    if (tid < SLOTS) {
        unsigned int cnt = 0, fr = 0;
        #pragma unroll
        for (int w = 0; w < NWARPS; w++) {
            unsigned int v = sh[w][tid];
            cnt += v >> CNT_SHIFT;
            fr  += v & ((1u << CNT_SHIFT) - 1u);
        }
        if (cnt) atomicAdd(&g_tot[tid], ((unsigned long long)cnt << TOT_SHIFT) | fr);
    }
    if (tid == 0) atomicAdd(&g_cnt1, s_c1);

    __threadfence();
    if (tid == 0) {
        unsigned int prev = atomicAdd(&g_done, 1u);
        s_last = (prev == gridDim.x - 1);
    }
    __syncthreads();
    if (!s_last) return;
    __threadfence();

    // ---- Last block: ~40 loads, compute loss, reset state ----
    if (tid == 0) {
        float cnt[2][BINS], fr[2][BINS];
        for (int g = 0; g < 2; g++) {
            for (int b = 0; b < BINS; b++) {
                unsigned long long v = g_tot[g * BINS + b];
                cnt[g][b] = (float)(v >> TOT_SHIFT);
                fr[g][b]  = (float)(v & ((1ULL << TOT_SHIFT) - 1ULL)) * INV_FRAC_SCALE;
            }
        }

        float W[2][NODES];
        for (int g = 0; g < 2; g++) {
            for (int k = 0; k < NODES; k++) {
                float w = 0.0f;
                if (k < BINS) w += cnt[g][k] - fr[g][k];
                if (k > 0)    w += fr[g][k - 1];
                W[g][k] = w;
            }
        }

        // Triangular weights per element sum to exactly 1 -> normalizers are
        // just the group sizes.
        float S1 = (float)g_cnt1;
        float S0 = (float)n - S1;
        float inv0 = (S0 > 0.0f) ? 1.0f / S0 : 0.0f;
        float inv1 = (S1 > 0.0f) ? 1.0f / S1 : 0.0f;

        float loss = 0.0f;
        for (int k = 0; k < NODES; k++) {
            if (k >= a_bin && k < b_bin)
                loss += fabsf(W[0][k] * inv0 - W[1][k] * inv1);
        }
        out[0] = loss;
        g_done = 0u;
        g_cnt1 = 0u;
    }
    __syncthreads();
    if (tid < SLOTS) g_tot[tid] = 0ULL;   // reset for next graph replay
}

extern "C" void kernel_launch(void* const* d_in, const int* in_sizes, int n_in,
                              void* d_out, int out_size) {
    const float* y_pred = (const float*)d_in[0];
    const int*   s      = (const int*)d_in[1];
    // d_in[2] = y_gt (unused)
    const float* pct_a  = (const float*)d_in[3];
    const float* pct_b  = (const float*)d_in[4];
    float* out = (float*)d_out;
    int n = in_sizes[0];

    int nvec = n >> 2;
    int blocks = (nvec + THREADS - 1) / THREADS;
    if (blocks > MAXBLOCKS) blocks = MAXBLOCKS;   // 4 CTAs/SM x 148 SMs
    if (blocks < 1) blocks = 1;

    hx_fused<<<blocks, THREADS>>>(y_pred, s, n, pct_a, pct_b, out);
}

// round 15
// speedup vs baseline: 2.7710x; 2.7710x over previous
#include <cuda_runtime.h>
#include <cuda_bf16.h>
#include <cstdint>

#define BINS 20
#define NODES 21
#define NWARPS 8
#define THREADS 256
#define MAXBLOCKS 592
#define SLOTS (2 * BINS)
#define FRAC_BITS 13
#define FRAC_MASK ((1u << FRAC_BITS) - 1u)
#define INV_FRAC_SCALE (1.0f/8192.0f)
#define CNT_SHIFT 20                /* smem u32 pack: cnt<<20 | frac13 */
#define PACK_SCALE 163840.0f        /* BINS << FRAC_BITS = 20*8192 */
#define MAGIC 12582912.0f           /* 1.5 * 2^23: float->fixed trick */
#define MAGIC_BITS 0x4B400000u
#define TOT_SHIFT 36                /* global u64 pack: cnt<<36 | frac_sum */

__device__ unsigned long long g_tot[SLOTS];
__device__ unsigned int g_cnt1;
__device__ unsigned int g_done;

__device__ __forceinline__ void hx_accum(unsigned int* my, float x, int g,
                                         unsigned int lo, unsigned int span,
                                         unsigned int& c1) {
    // Float->fixed via FFMA magic: bits(x*163840 + 1.5*2^23) - MAGIC_BITS
    // == rn(x*163840); k = u>>13; 13-bit frac in the low bits. RN-vs-floor
    // only moves boundary elements continuously between adjacent nodes.
    unsigned int u = __float_as_uint(fmaf(x, PACK_SCALE, MAGIC)) - MAGIC_BITS;
    unsigned int k = u >> FRAC_BITS;
    c1 += (unsigned int)g;                                  // exact group count
    if (k - lo <= span) {   // single unsigned compare: lo <= k <= hi
        unsigned int pk = (u & FRAC_MASK) | (1u << CNT_SHIFT);
        atomicAdd(&my[(unsigned int)g * BINS + k], pk);
    }
}

// 256-bit global loads (sm_100a native).
__device__ __forceinline__ void ldg256_f32(const float* p, float* v) {
    asm volatile("ld.global.nc.v8.f32 {%0,%1,%2,%3,%4,%5,%6,%7}, [%8];"
                 : "=f"(v[0]), "=f"(v[1]), "=f"(v[2]), "=f"(v[3]),
                   "=f"(v[4]), "=f"(v[5]), "=f"(v[6]), "=f"(v[7])
                 : "l"(p));
}
__device__ __forceinline__ void ldg256_u32(const int* p, unsigned int* v) {
    asm volatile("ld.global.nc.v8.b32 {%0,%1,%2,%3,%4,%5,%6,%7}, [%8];"
                 : "=r"(v[0]), "=r"(v[1]), "=r"(v[2]), "=r"(v[3]),
                   "=r"(v[4]), "=r"(v[5]), "=r"(v[6]), "=r"(v[7])
                 : "l"(p));
}

__global__ __launch_bounds__(THREADS, 4)
void hx_fused(const float* __restrict__ yp, const int* __restrict__ s, int n,
              const float* __restrict__ p_a, const float* __restrict__ p_b,
              float* __restrict__ out) {
    __shared__ unsigned int sh[NWARPS][SLOTS];
    __shared__ unsigned int s_c1;
    __shared__ bool s_last;
    const int tid = threadIdx.x;
    const int warp = tid >> 5;

    for (int i = tid; i < NWARPS * SLOTS; i += THREADS)
        (&sh[0][0])[i] = 0u;
    if (tid == 0) s_c1 = 0u;
    __syncthreads();

    // int(20*pct) in Python is computed in double; f32 0.7f*20 = 13.99999976
    // would floor to 13, so snap up with an epsilon before truncation.
    const int a_bin = (int)floorf((float)BINS * __ldg(p_a) + 1e-4f);
    const int b_bin = (int)floorf((float)BINS * __ldg(p_b) + 1e-4f);
    const unsigned int lo   = (unsigned int)max(a_bin - 1, 0);
    const unsigned int hi   = (unsigned int)(min(b_bin, BINS) - 1);
    const unsigned int span = hi - lo;

    unsigned int* my = sh[warp];
    unsigned int c1 = 0;

    const int nvec8 = n >> 3;            // groups of 8 elements (32B)
    const int T = gridDim.x * THREADS;

    #pragma unroll 2
    for (int i = blockIdx.x * THREADS + tid; i < nvec8; i += T) {
        float        xv[8];
        unsigned int gv[8];
        ldg256_f32(yp + (size_t)i * 8, xv);
        ldg256_u32(s  + (size_t)i * 8, gv);
        #pragma unroll
        for (int e = 0; e < 8; e++)
            hx_accum(my, xv[e], (int)gv[e], lo, span, c1);
    }

    // tail (n not divisible by 8)
    {
        int rem_base = nvec8 << 3;
        int gtid = blockIdx.x * THREADS + tid;
        if (gtid < n - rem_base) {
            int idx = rem_base + gtid;
            hx_accum(my, yp[idx], s[idx], lo, span, c1);
        }
    }

    // Exact group-1 count: warp redux -> smem -> one global atomic per block.
    c1 = __reduce_add_sync(0xffffffffu, c1);
    if ((tid & 31) == 0 && c1) atomicAdd(&s_c1, c1);
    __syncthreads();

    // Reduce warp copies; ONE packed global atomic per slot per block.
    if (tid < SLOTS) {
        unsigned int cnt = 0, fr = 0;
        #pragma unroll
        for (int w = 0; w < NWARPS; w++) {
            unsigned int v = sh[w][tid];
            cnt += v >> CNT_SHIFT;
            fr  += v & ((1u << CNT_SHIFT) - 1u);
        }
        if (cnt) atomicAdd(&g_tot[tid], ((unsigned long long)cnt << TOT_SHIFT) | fr);
    }
    if (tid == 0) atomicAdd(&g_cnt1, s_c1);

    __threadfence();
    if (tid == 0) {
        unsigned int prev = atomicAdd(&g_done, 1u);
        s_last = (prev == gridDim.x - 1);
    }
    __syncthreads();
    if (!s_last) return;
    __threadfence();

    // ---- Last block: ~40 loads, compute loss, reset state ----
    if (tid == 0) {
        float cnt[2][BINS], fr[2][BINS];
        for (int g = 0; g < 2; g++) {
            for (int b = 0; b < BINS; b++) {
                unsigned long long v = g_tot[g * BINS + b];
                cnt[g][b] = (float)(v >> TOT_SHIFT);
                fr[g][b]  = (float)(v & ((1ULL << TOT_SHIFT) - 1ULL)) * INV_FRAC_SCALE;
            }
        }

        float W[2][NODES];
        for (int g = 0; g < 2; g++) {
            for (int k = 0; k < NODES; k++) {
                float w = 0.0f;
                if (k < BINS) w += cnt[g][k] - fr[g][k];
                if (k > 0)    w += fr[g][k - 1];
                W[g][k] = w;
            }
        }

        // Triangular weights per element sum to exactly 1 -> normalizers are
        // just the group sizes.
        float S1 = (float)g_cnt1;
        float S0 = (float)n - S1;
        float inv0 = (S0 > 0.0f) ? 1.0f / S0 : 0.0f;
        float inv1 = (S1 > 0.0f) ? 1.0f / S1 : 0.0f;

        float loss = 0.0f;
        for (int k = 0; k < NODES; k++) {
            if (k >= a_bin && k < b_bin)
                loss += fabsf(W[0][k] * inv0 - W[1][k] * inv1);
        }
        out[0] = loss;
        g_done = 0u;
        g_cnt1 = 0u;
    }
    __syncthreads();
    if (tid < SLOTS) g_tot[tid] = 0ULL;   // reset for next graph replay
}

extern "C" void kernel_launch(void* const* d_in, const int* in_sizes, int n_in,
                              void* d_out, int out_size) {
    const float* y_pred = (const float*)d_in[0];
    const int*   s      = (const int*)d_in[1];
    // d_in[2] = y_gt (unused)
    const float* pct_a  = (const float*)d_in[3];
    const float* pct_b  = (const float*)d_in[4];
    float* out = (float*)d_out;
    int n = in_sizes[0];

    int nvec8 = n >> 3;
    int blocks = (nvec8 + THREADS - 1) / THREADS;
    if (blocks > MAXBLOCKS) blocks = MAXBLOCKS;   // 4 CTAs/SM x 148 SMs
    if (blocks < 1) blocks = 1;

    hx_fused<<<blocks, THREADS>>>(y_pred, s, n, pct_a, pct_b, out);
}